// round 6
// baseline (speedup 1.0000x reference)
#include <cuda_runtime.h>
#include <math.h>

// Problem constants
#define B_ 256
#define N_ 1024
#define H_ 256
#define K_ 5
#define NEG_SLOPE 0.01f
#define FULLMASK 0xffffffffu

static __device__ __forceinline__ float neg_inf() {
    return __int_as_float(0xff800000);
}

// ---------------------------------------------------------------------------
// Fused kernel: one block per batch.
//  Phase 1: stream rows [0, nn) of h[b], per-node max -> s_key (8 nodes per
//           warp-iteration, 16 LDG.128 front-batched = 8KB in flight/warp).
//  Phase 2: warps 0..4 each compute the top-5 via per-lane u64-packed
//           insertion lists + k-round shuffle tournament (strict total order
//           == jax.lax.top_k tie semantics); warp wid exits at round wid and
//           gathers its row. Warp 5 computes cb = dot(q, W[H:2H]).
//  Phase 3: register bitonic sort (8 elems/lane), dot with W[:H] -> s_logit.
//  Phase 4: per-thread leaky+softmax over K, weighted sum -> out[b,:].
//  2 block barriers total.
// ---------------------------------------------------------------------------
__global__ void __launch_bounds__(256)
fused_sortpool_kernel(const float* __restrict__ h,
                      const int* __restrict__ n_nodes,
                      const float* __restrict__ q,
                      const float* __restrict__ W,
                      float* __restrict__ out) {
    __shared__ float s_key[N_];          // 4 KB
    __shared__ float s_sel[K_][H_];      // 5 KB: sorted selected rows
    __shared__ float s_logit[K_];        // raw dot (pre-cb, pre-leaky)
    __shared__ float s_cb;

    const int b    = blockIdx.x;
    const int t    = threadIdx.x;
    const int wid  = t >> 5;
    const int lane = t & 31;
    const float NI = neg_inf();
    const int nn   = __ldg(&n_nodes[b]);

    const float4* hb4 = reinterpret_cast<const float4*>(h) +
                        (size_t)b * N_ * (H_ / 4);

    // ================= Phase 1: per-node max -> s_key =================
    // 128 chunks of 8 nodes; warp w handles chunks w, w+8, ... (16 chunks).
    for (int c = wid; c < N_ / 8; c += 8) {
        const int n0 = c << 3;
        if (n0 >= nn) {
            if (lane < 2)
                reinterpret_cast<float4*>(&s_key[n0])[lane] =
                    make_float4(NI, NI, NI, NI);
            continue;
        }
        const float4* p = hb4 + (size_t)n0 * (H_ / 4);
        float4 va[8], vb[8];
        bool vld[8];
#pragma unroll
        for (int j = 0; j < 8; j++) {
            vld[j] = (n0 + j) < nn;
            if (vld[j]) {
                va[j] = p[(j << 6) + lane];
                vb[j] = p[(j << 6) + lane + 32];
            }
        }
        float m[8];
#pragma unroll
        for (int j = 0; j < 8; j++) {
            m[j] = vld[j]
                 ? fmaxf(fmaxf(fmaxf(va[j].x, va[j].y), fmaxf(va[j].z, va[j].w)),
                         fmaxf(fmaxf(vb[j].x, vb[j].y), fmaxf(vb[j].z, vb[j].w)))
                 : NI;
        }
#pragma unroll
        for (int o = 16; o; o >>= 1) {
#pragma unroll
            for (int j = 0; j < 8; j++)
                m[j] = fmaxf(m[j], __shfl_xor_sync(FULLMASK, m[j], o));
        }
        if (lane == 0) {
            reinterpret_cast<float4*>(&s_key[n0])[0] =
                make_float4(m[0], m[1], m[2], m[3]);
            reinterpret_cast<float4*>(&s_key[n0])[1] =
                make_float4(m[4], m[5], m[6], m[7]);
        }
    }
    __syncthreads();   // barrier A

    // ================= Phase 2 + 3 =================
    if (wid < K_) {
        // ---- per-lane top-5 insertion list over 32 strided keys ----
        // packed = (ord(float) << 32) | (N-1-i): strict total order,
        // value desc then index asc — identical to jax.lax.top_k.
        unsigned long long L[K_];
#pragma unroll
        for (int j = 0; j < K_; j++) L[j] = 0ull;
#pragma unroll
        for (int jj = 0; jj < 32; jj++) {
            int i = lane + (jj << 5);                      // conflict-free LDS
            unsigned int bits = __float_as_uint(s_key[i]);
            unsigned int ord  = (bits & 0x80000000u) ? ~bits
                                                     : (bits | 0x80000000u);
            unsigned long long pk =
                ((unsigned long long)ord << 32) | (unsigned int)(N_ - 1 - i);
            if (pk > L[K_ - 1]) {
                L[K_ - 1] = pk;
#pragma unroll
                for (int j2 = K_ - 1; j2 > 0; j2--) {
                    if (L[j2] > L[j2 - 1]) {
                        unsigned long long tmp = L[j2];
                        L[j2] = L[j2 - 1];
                        L[j2 - 1] = tmp;
                    }
                }
            }
        }
        // ---- tournament: warp wid needs rounds 0..wid only ----
        int p = 0;
        unsigned long long w = 0ull;
        for (int k = 0; k <= wid; k++) {
            w = (p < K_) ? L[p] : 0ull;
#pragma unroll
            for (int o = 16; o; o >>= 1) {
                unsigned long long ow = __shfl_xor_sync(FULLMASK, w, o);
                if (ow > w) w = ow;
            }
            if (p < K_ && L[p] == w) p++;   // unique winner (indices distinct)
        }
        const int  node  = (N_ - 1) - (int)(w & 0xffffffffu);
        const bool valid = (unsigned int)(w >> 32) > 0x007fffffu; // > ord(-inf)

        // ---- gather row (rows hot in L2 from phase 1) ----
        const float* row = h + ((size_t)b * N_ + node) * H_;
        float val[8];
#pragma unroll
        for (int r = 0; r < 8; r++)
            val[r] = valid ? row[(lane << 3) + r] : 0.0f;

        // ---- register bitonic sort, 256 elements, ascending ----
#pragma unroll
        for (int kk = 2; kk <= 256; kk <<= 1) {
#pragma unroll
            for (int j = kk >> 1; j > 0; j >>= 1) {
                if (j >= 8) {
                    int  ld  = j >> 3;
                    bool asc = (((lane << 3) & kk) == 0);
                    bool low = ((lane & ld) == 0);
#pragma unroll
                    for (int r = 0; r < 8; r++) {
                        float other = __shfl_xor_sync(FULLMASK, val[r], ld);
                        val[r] = (low == asc) ? fminf(val[r], other)
                                              : fmaxf(val[r], other);
                    }
                } else {
#pragma unroll
                    for (int r = 0; r < 8; r++) {
                        if ((r & j) == 0) {
                            int  r2  = r | j;
                            bool asc = ((((lane << 3) | r) & kk) == 0);
                            float a = val[r], c = val[r2];
                            float lo = fminf(a, c), hi = fmaxf(a, c);
                            val[r]  = asc ? lo : hi;
                            val[r2] = asc ? hi : lo;
                        }
                    }
                }
            }
        }

        // ---- store sorted row + raw dot with W[:H] ----
        float s = 0.0f;
#pragma unroll
        for (int r = 0; r < 8; r++) {
            int i = (lane << 3) + r;
            s_sel[wid][i] = val[r];
            s += val[r] * W[i];
        }
#pragma unroll
        for (int o = 16; o; o >>= 1)
            s += __shfl_xor_sync(FULLMASK, s, o);
        if (lane == 0) s_logit[wid] = s;
    } else if (wid == K_) {
        // ---- cb = dot(q[b,:], W[H:2H]) ----
        float s = 0.0f;
#pragma unroll
        for (int r = 0; r < 8; r++) {
            int i = (lane << 3) + r;
            s += q[b * H_ + i] * W[H_ + i];
        }
#pragma unroll
        for (int o = 16; o; o >>= 1)
            s += __shfl_xor_sync(FULLMASK, s, o);
        if (lane == 0) s_cb = s;
    }
    __syncthreads();   // barrier B

    // ================= Phase 4: leaky + softmax + weighted sum =================
    const float cb = s_cb;
    float lg[K_];
#pragma unroll
    for (int k = 0; k < K_; k++) {
        float x = s_logit[k] + cb;
        lg[k] = (x >= 0.0f) ? x : NEG_SLOPE * x;
    }
    float lm = lg[0];
#pragma unroll
    for (int k = 1; k < K_; k++) lm = fmaxf(lm, lg[k]);
    float es = 0.0f;
    float e[K_];
#pragma unroll
    for (int k = 0; k < K_; k++) { e[k] = __expf(lg[k] - lm); es += e[k]; }
    float inv = 1.0f / es;
    float acc = 0.0f;
#pragma unroll
    for (int k = 0; k < K_; k++) acc += (e[k] * inv) * s_sel[k][t];

    out[b * H_ + t] = acc;
}

extern "C" void kernel_launch(void* const* d_in, const int* in_sizes, int n_in,
                              void* d_out, int out_size) {
    const float* h  = (const float*)d_in[0];           // [B, N, H]
    const int*   nn = (const int*)d_in[1];             // [B]
    const float* q  = (const float*)d_in[2];           // [B, H]
    const float* W  = (const float*)d_in[3];           // [1, 2H]
    float*       o  = (float*)d_out;                   // [B, H]

    (void)in_sizes; (void)n_in; (void)out_size;

    fused_sortpool_kernel<<<B_, 256>>>(h, nn, q, W, o);
}